// round 10
// baseline (speedup 1.0000x reference)
#include <cuda_runtime.h>
#include <cstdint>

// Arithmetic nearest-codebook quantizer for the FP4-style codebook
//   [-6,-4,-3,-2,-1.5,-1,-0.75, 0, 0.5,0.75,1,1.5,2,3,4,6]
// (see prior rounds for derivation; tie semantics match jnp.argmin).
__device__ __forceinline__ float quant1(float x, float scale, float inv) {
    unsigned int u  = __float_as_uint(x);
    float as = fabsf(x) * scale;                             // FMUL (abs free)
    unsigned int nb = __umulhi(u, 2u);                       // == u >> 31 (fma pipe)
    unsigned int LO = nb * 0x00400000u + 0x3F000000u;        // 0.5 / 0.75 bits
    unsigned int Tb = nb * 0x003FFFFFu + 0x3E800001u;        // dead-zone threshold
    unsigned int sw = u & 0x80000000u;
    float t = fminf(fmaxf(as, __uint_as_float(LO)), 6.0f);   // exact: positive floats
    unsigned int q0 = __float_as_uint(t) + 0x001FFFFFu + nb; // half-down/half-up
    unsigned int q  = (q0 & 0xFFC00000u) | sw;
    q = (as < __uint_as_float(Tb)) ? 0u : q;
    return __uint_as_float(q) * inv;
}

__device__ __forceinline__ float4 quant4(float4 v, float scale, float inv) {
    float4 r;
    r.x = quant1(v.x, scale, inv);
    r.y = quant1(v.y, scale, inv);
    r.z = quant1(v.z, scale, inv);
    r.w = quant1(v.w, scale, inv);
    return r;
}

#define NSTAGE      3
#define CHUNK_F4    2048                 // float4 per chunk = 8192 floats
#define CHUNK_BYTES 32768                // 32 KB
#define PIPE_THREADS 512

__device__ __forceinline__ void mbar_wait_parity(uint32_t mb, uint32_t phase) {
    asm volatile(
        "{\n\t"
        ".reg .pred P;\n\t"
        "WAIT_%=: \n\t"
        "mbarrier.try_wait.parity.acquire.cta.shared::cta.b64 P, [%0], %1, 0x989680;\n\t"
        "@P bra.uni DONE_%=;\n\t"
        "bra.uni WAIT_%=;\n\t"
        "DONE_%=: \n\t"
        "}"
        :: "r"(mb), "r"(phase) : "memory");
}

__device__ __forceinline__ void tma_load_chunk(uint32_t dst_smem,
                                               const float* src_gmem,
                                               uint32_t mb) {
    asm volatile("mbarrier.arrive.expect_tx.shared.b64 _, [%0], %1;"
                 :: "r"(mb), "n"(CHUNK_BYTES) : "memory");
    asm volatile(
        "cp.async.bulk.shared::cluster.global.mbarrier::complete_tx::bytes "
        "[%0], [%1], %2, [%3];"
        :: "r"(dst_smem), "l"(src_gmem), "n"(CHUNK_BYTES), "r"(mb) : "memory");
}

// TMA bulk pipeline kernel. Both global loads and stores go through the TMA
// engine (cp.async.bulk): no LDG/STG on the LSU, no L1tex wavefront queue,
// no long-scoreboard stalls — latency is hidden by the 3-stage smem ring.
// Compute is in-place in smem: LDS.128 -> quant -> STS.128 (conflict-free:
// lane l reads float4 l, warp covers 512 contiguous bytes).
__global__ void __launch_bounds__(PIPE_THREADS, 2)
quant_tma_kernel(const float* __restrict__ x,
                 float* __restrict__ out,
                 const float* __restrict__ scale_p,
                 int nchunks) {
    extern __shared__ __align__(16) char smem[];
    float4* buf = (float4*)smem;                                   // 3 x 32 KB
    uint32_t mbar0 = (uint32_t)__cvta_generic_to_shared(
        smem + NSTAGE * CHUNK_BYTES);                              // 3 mbarriers

    int tid = (int)threadIdx.x;
    float scale = __ldg(scale_p);
    float inv   = 1.0f / scale;

    // Chunks for this CTA: cidx(i) = blockIdx.x + i*gridDim.x
    int cnt = (nchunks - (int)blockIdx.x + (int)gridDim.x - 1) / (int)gridDim.x;
    if (cnt <= 0) return;

    if (tid == 0) {
        #pragma unroll
        for (int s = 0; s < NSTAGE; s++)
            asm volatile("mbarrier.init.shared.b64 [%0], 1;"
                         :: "r"(mbar0 + s * 8) : "memory");
    }
    __syncthreads();

    // Prologue: fill the ring.
    if (tid == 0) {
        for (int i = 0; i < NSTAGE && i < cnt; i++) {
            int cidx = (int)blockIdx.x + i * (int)gridDim.x;
            uint32_t dst = (uint32_t)__cvta_generic_to_shared(buf + i * CHUNK_F4);
            tma_load_chunk(dst, x + (size_t)cidx * (CHUNK_F4 * 4), mbar0 + i * 8);
        }
    }

    #pragma unroll 1
    for (int i = 0; i < cnt; i++) {
        int b = i % NSTAGE;
        uint32_t mb = mbar0 + b * 8;
        mbar_wait_parity(mb, (uint32_t)((i / NSTAGE) & 1));

        float4* bp = buf + b * CHUNK_F4;
        float4 v0 = bp[tid];
        float4 v1 = bp[tid + 512];
        float4 v2 = bp[tid + 1024];
        float4 v3 = bp[tid + 1536];
        bp[tid]        = quant4(v0, scale, inv);
        bp[tid + 512]  = quant4(v1, scale, inv);
        bp[tid + 1024] = quant4(v2, scale, inv);
        bp[tid + 1536] = quant4(v3, scale, inv);

        // Order generic-proxy STS before the async-proxy bulk store.
        asm volatile("fence.proxy.async.shared::cta;" ::: "memory");
        __syncthreads();

        if (tid == 0) {
            int cidx = (int)blockIdx.x + i * (int)gridDim.x;
            uint32_t srcS = (uint32_t)__cvta_generic_to_shared(bp);
            float* gdst = out + (size_t)cidx * (CHUNK_F4 * 4);
            asm volatile("cp.async.bulk.global.shared::cta.bulk_group [%0], [%1], %2;"
                         :: "l"(gdst), "r"(srcS), "n"(CHUNK_BYTES) : "memory");
            asm volatile("cp.async.bulk.commit_group;" ::: "memory");

            // Refill: chunk i+2 goes into buf[(i+2)%3], last stored at iter
            // i-1. wait_group.read 1 ensures that store finished READING smem
            // (only the just-committed store may remain pending).
            int ni = i + 2;
            if (ni >= NSTAGE && ni < cnt) {
                asm volatile("cp.async.bulk.wait_group.read 1;" ::: "memory");
                int ncidx = (int)blockIdx.x + ni * (int)gridDim.x;
                int nb2 = ni % NSTAGE;
                uint32_t dst = (uint32_t)__cvta_generic_to_shared(buf + nb2 * CHUNK_F4);
                tma_load_chunk(dst, x + (size_t)ncidx * (CHUNK_F4 * 4), mbar0 + nb2 * 8);
            }
        }
    }

    // All bulk stores must finish reading smem before CTA exit.
    if (tid == 0)
        asm volatile("cp.async.bulk.wait_group.read 0;" ::: "memory");
    __syncthreads();
}

// General fallback (predicated) for any remainder elements.
__global__ void __launch_bounds__(256)
quant_kernel_tail(const float* __restrict__ x,
                  float* __restrict__ out,
                  const float* __restrict__ scale_p,
                  int start, int n) {
    float scale = __ldg(scale_p);
    float inv   = 1.0f / scale;
    int i = start + blockIdx.x * 256 + (int)threadIdx.x;
    if (i < n) out[i] = quant1(x[i], scale, inv);
}

extern "C" void kernel_launch(void* const* d_in, const int* in_sizes, int n_in,
                              void* d_out, int out_size) {
    const float* x     = (const float*)d_in[0];   // [n] fp32
    // d_in[1] (codebook) is folded into the bit arithmetic above.
    const float* scale = (const float*)d_in[2];
    float* out = (float*)d_out;

    int n = in_sizes[0];
    const int CHUNK_ELEMS = CHUNK_F4 * 4;         // 8192

    int nchunks = n / CHUNK_ELEMS;                // 2048 for 4096x4096
    int covered = nchunks * CHUNK_ELEMS;

    if (nchunks > 0) {
        static bool attr_set = false;
        size_t smem_bytes = NSTAGE * CHUNK_BYTES + 64;
        if (!attr_set) {
            cudaFuncSetAttribute(quant_tma_kernel,
                                 cudaFuncAttributeMaxDynamicSharedMemorySize,
                                 (int)smem_bytes);
            attr_set = true;
        }
        int grid = 148 * 2;                       // 2 CTAs/SM (96 KB smem each)
        if (grid > nchunks) grid = nchunks;
        quant_tma_kernel<<<grid, PIPE_THREADS, smem_bytes>>>(x, out, scale, nchunks);
    }
    if (covered < n) {
        int rem = n - covered;
        int blocks = (rem + 255) / 256;
        quant_kernel_tail<<<blocks, 256>>>(x, out, scale, covered, n);
    }
}

// round 11
// speedup vs baseline: 1.0770x; 1.0770x over previous
#include <cuda_runtime.h>
#include <cstdint>

// Arithmetic nearest-codebook quantizer for the FP4-style codebook
//   [-6,-4,-3,-2,-1.5,-1,-0.75, 0, 0.5,0.75,1,1.5,2,3,4,6]
// Positive magnitudes are spaced 0x00400000 apart in fp32 bit space; every
// decision boundary is an exact bit midpoint. Tie semantics match jnp.argmin
// (first index wins): positives round half-DOWN, negatives half-UP in
// magnitude. Sign-dependent low clamp (0.5 pos / 0.75 neg), dead zone
// (as <= 0.25 pos ; as < 0.375 neg). Pipe-balanced (fma/alu mixed).
__device__ __forceinline__ float quant1(float x, float scale, float inv) {
    unsigned int u  = __float_as_uint(x);
    float as = fabsf(x) * scale;                             // FMUL (abs free)
    unsigned int nb = __umulhi(u, 2u);                       // == u >> 31 (fma)
    unsigned int LO = nb * 0x00400000u + 0x3F000000u;        // 0.5/0.75 bits
    unsigned int Tb = nb * 0x003FFFFFu + 0x3E800001u;        // dead threshold
    unsigned int sw = u & 0x80000000u;
    float t = fminf(fmaxf(as, __uint_as_float(LO)), 6.0f);   // exact on positives
    unsigned int q0 = __float_as_uint(t) + 0x001FFFFFu + nb; // half-down/up
    unsigned int q  = (q0 & 0xFFC00000u) | sw;
    q = (as < __uint_as_float(Tb)) ? 0u : q;
    return __uint_as_float(q) * inv;
}

// 256-bit global accesses (sm_100+): one LDG.E.256 / STG.E.256 per 8 floats —
// half the LSU issue slots and L1tex wavefronts of the float4 version.
__device__ __forceinline__ void ldg_v8(const float* __restrict__ p, float r[8]) {
    asm volatile("ld.global.v8.b32 {%0,%1,%2,%3,%4,%5,%6,%7}, [%8];"
                 : "=f"(r[0]), "=f"(r[1]), "=f"(r[2]), "=f"(r[3]),
                   "=f"(r[4]), "=f"(r[5]), "=f"(r[6]), "=f"(r[7])
                 : "l"(p));
}

__device__ __forceinline__ void stg_v8_cs(float* __restrict__ p, const float r[8]) {
    asm volatile("st.global.cs.v8.b32 [%8], {%0,%1,%2,%3,%4,%5,%6,%7};"
                 :: "f"(r[0]), "f"(r[1]), "f"(r[2]), "f"(r[3]),
                    "f"(r[4]), "f"(r[5]), "f"(r[6]), "f"(r[7]),
                    "l"(p) : "memory");
}

// LTS-roofline kernel, R5/R9 proven config:
//  - persistent single wave: 148 SMs x 8 CTAs, grid-stride over tiles
//  - loads default-cached (input stays L2-resident across graph replays,
//    since .cs streaming stores never allocate L2 lines)
//  - stores streaming (output is touch-once)
//  - 256-bit vector memory ops, 2 front-batched loads per thread per tile
__global__ void __launch_bounds__(256, 8)
quant_kernel(const float* __restrict__ x,
             float* __restrict__ out,
             const float* __restrict__ scale_p,
             int ntiles) {   // tiles of 4096 floats
    float scale = __ldg(scale_p);
    float inv   = 1.0f / scale;
    int lane8 = (int)threadIdx.x * 8;

    #pragma unroll 1
    for (int tile = blockIdx.x; tile < ntiles; tile += gridDim.x) {
        size_t base = (size_t)tile * 4096 + lane8;

        float a[8], b[8];
        ldg_v8(x + base, a);            // front-batched: 2 independent LDG.256
        ldg_v8(x + base + 2048, b);

        float qa[8], qb[8];
        #pragma unroll
        for (int k = 0; k < 8; k++) qa[k] = quant1(a[k], scale, inv);
        #pragma unroll
        for (int k = 0; k < 8; k++) qb[k] = quant1(b[k], scale, inv);

        stg_v8_cs(out + base, qa);
        stg_v8_cs(out + base + 2048, qb);
    }
}

// General fallback (predicated) for any remainder elements.
__global__ void __launch_bounds__(256)
quant_kernel_tail(const float* __restrict__ x,
                  float* __restrict__ out,
                  const float* __restrict__ scale_p,
                  int start, int n) {
    float scale = __ldg(scale_p);
    float inv   = 1.0f / scale;
    int i = start + blockIdx.x * 256 + (int)threadIdx.x;
    if (i < n) out[i] = quant1(x[i], scale, inv);
}

extern "C" void kernel_launch(void* const* d_in, const int* in_sizes, int n_in,
                              void* d_out, int out_size) {
    const float* x     = (const float*)d_in[0];   // [n] fp32
    // d_in[1] (codebook) is folded into the bit arithmetic above.
    const float* scale = (const float*)d_in[2];
    float* out = (float*)d_out;

    int n = in_sizes[0];
    const int ELEMS_PER_TILE = 4096;              // 256 thr x 16 floats

    int ntiles  = n / ELEMS_PER_TILE;
    int covered = ntiles * ELEMS_PER_TILE;

    if (ntiles > 0) {
        int grid = 148 * 8;                        // exactly 8 CTAs per SM
        if (grid > ntiles) grid = ntiles;
        quant_kernel<<<grid, 256>>>(x, out, scale, ntiles);
    }
    if (covered < n) {
        int rem = n - covered;
        int blocks = (rem + 255) / 256;
        quant_kernel_tail<<<blocks, 256>>>(x, out, scale, covered, n);
    }
}

// round 12
// speedup vs baseline: 1.0890x; 1.0111x over previous
#include <cuda_runtime.h>
#include <cstdint>

// Arithmetic nearest-codebook quantizer for the FP4-style codebook
//   [-6,-4,-3,-2,-1.5,-1,-0.75, 0, 0.5,0.75,1,1.5,2,3,4,6]
// Positive magnitudes are spaced 0x00400000 apart in fp32 bit space; every
// decision boundary is an exact bit midpoint. Tie semantics match jnp.argmin
// (first index wins): positives round half-DOWN, negatives half-UP in
// magnitude. Sign-dependent low clamp (0.5 pos / 0.75 neg), dead zone
// (as <= 0.25 pos ; as < 0.375 neg). Pipe-balanced (fma/alu mixed).
__device__ __forceinline__ float quant1(float x, float scale, float inv) {
    unsigned int u  = __float_as_uint(x);
    float as = fabsf(x) * scale;                             // FMUL (abs free)
    unsigned int nb = __umulhi(u, 2u);                       // == u >> 31 (fma)
    unsigned int LO = nb * 0x00400000u + 0x3F000000u;        // 0.5/0.75 bits
    unsigned int Tb = nb * 0x003FFFFFu + 0x3E800001u;        // dead threshold
    unsigned int sw = u & 0x80000000u;
    float t = fminf(fmaxf(as, __uint_as_float(LO)), 6.0f);   // exact on positives
    unsigned int q0 = __float_as_uint(t) + 0x001FFFFFu + nb; // half-down/up
    unsigned int q  = (q0 & 0xFFC00000u) | sw;
    q = (as < __uint_as_float(Tb)) ? 0u : q;
    return __uint_as_float(q) * inv;
}

__device__ __forceinline__ void stg_v8_cs(float* __restrict__ p, const float r[8]) {
    asm volatile("st.global.cs.v8.b32 [%8], {%0,%1,%2,%3,%4,%5,%6,%7};"
                 :: "f"(r[0]), "f"(r[1]), "f"(r[2]), "f"(r[3]),
                    "f"(r[4]), "f"(r[5]), "f"(r[6]), "f"(r[7]),
                    "l"(p) : "memory");
}

// R9's proven config (warm 19.2us) with ONE change: stores widened to
// STG.256.cs. Loads stay 4 front-batched LDG.128 per thread per tile —
// that MLP=4 is what hides the warm L2-hit latency (R11 showed halving it
// to two v8 loads regressed the warm loop). Layout: each thread owns two
// contiguous 8-float segments so the stores can be 256-bit.
__global__ void __launch_bounds__(256, 8)
quant_kernel(const float4* __restrict__ x,
             float* __restrict__ out,
             const float* __restrict__ scale_p,
             int ntiles) {   // tiles of 1024 float4 (4096 floats)
    float scale = __ldg(scale_p);
    float inv   = 1.0f / scale;
    int tid = (int)threadIdx.x;

    #pragma unroll 1
    for (int tile = blockIdx.x; tile < ntiles; tile += gridDim.x) {
        // float4 indices: thread owns {2t, 2t+1} and {512+2t, 512+2t+1}
        size_t b0 = (size_t)tile * 1024 + 2 * tid;        // contiguous pair
        size_t b1 = b0 + 512;                             // second pair

        float4 v0 = x[b0];
        float4 v1 = x[b0 + 1];
        float4 v2 = x[b1];
        float4 v3 = x[b1 + 1];

        float qa[8], qb[8];
        qa[0] = quant1(v0.x, scale, inv); qa[1] = quant1(v0.y, scale, inv);
        qa[2] = quant1(v0.z, scale, inv); qa[3] = quant1(v0.w, scale, inv);
        qa[4] = quant1(v1.x, scale, inv); qa[5] = quant1(v1.y, scale, inv);
        qa[6] = quant1(v1.z, scale, inv); qa[7] = quant1(v1.w, scale, inv);
        qb[0] = quant1(v2.x, scale, inv); qb[1] = quant1(v2.y, scale, inv);
        qb[2] = quant1(v2.z, scale, inv); qb[3] = quant1(v2.w, scale, inv);
        qb[4] = quant1(v3.x, scale, inv); qb[5] = quant1(v3.y, scale, inv);
        qb[6] = quant1(v3.z, scale, inv); qb[7] = quant1(v3.w, scale, inv);

        stg_v8_cs(out + b0 * 4, qa);      // one STG.256 per 8 floats
        stg_v8_cs(out + b1 * 4, qb);
    }
}

// General fallback (predicated) for any remainder elements.
__global__ void __launch_bounds__(256)
quant_kernel_tail(const float* __restrict__ x,
                  float* __restrict__ out,
                  const float* __restrict__ scale_p,
                  int start, int n) {
    float scale = __ldg(scale_p);
    float inv   = 1.0f / scale;
    int i = start + blockIdx.x * 256 + (int)threadIdx.x;
    if (i < n) out[i] = quant1(x[i], scale, inv);
}

extern "C" void kernel_launch(void* const* d_in, const int* in_sizes, int n_in,
                              void* d_out, int out_size) {
    const float* x     = (const float*)d_in[0];   // [n] fp32
    // d_in[1] (codebook) is folded into the bit arithmetic above.
    const float* scale = (const float*)d_in[2];
    float* out = (float*)d_out;

    int n = in_sizes[0];
    const int ELEMS_PER_TILE = 4096;              // 1024 float4

    int ntiles  = n / ELEMS_PER_TILE;
    int covered = ntiles * ELEMS_PER_TILE;

    if (ntiles > 0) {
        int grid = 148 * 8;                        // exactly 8 CTAs per SM
        if (grid > ntiles) grid = ntiles;
        quant_kernel<<<grid, 256>>>(
            (const float4*)x, out, scale, ntiles);
    }
    if (covered < n) {
        int rem = n - covered;
        int blocks = (rem + 255) / 256;
        quant_kernel_tail<<<blocks, 256>>>(x, out, scale, covered, n);
    }
}